// round 2
// baseline (speedup 1.0000x reference)
#include <cuda_runtime.h>
#include <cuda_bf16.h>
#include <math.h>

#define BB 2
#define TT 64
#define CC 384
#define HH 768

// scratch (device globals — no allocation allowed)
__device__ float g_q[CC];
__device__ float g_h[BB*HH];
__device__ float g_pred[BB*CC];
__device__ float g_k[BB*TT*CC];
__device__ float g_v[BB*TT*CC];
__device__ float g_h1[BB*TT*HH];
__device__ float g_gfac[BB*TT*HH];
__device__ float g_dp[BB*TT*CC];
__device__ float g_dh1p[BB*TT*HH];
__device__ float g_coeff[TT];
__device__ float g_dfac;

// ---------------------------------------------------------------------------
// coeff[t] = -LR * (1-MOM) * c_t,  c_t = sum_{s=t}^{T-1} d^{T-1-s} MOM^{s-t}
// dfac = d^T  (d = 1-DECAY). Closed form of the two constant-gate pscans.
// ---------------------------------------------------------------------------
__global__ void k_coeff() {
    const double d = 1.0 - 0.001;   // 1-DECAY
    const double M = 0.9;           // MOM
    double cs[TT];
    cs[TT-1] = 1.0;
    for (int s = TT-2; s >= 0; --s)
        cs[s] = M * cs[s+1] + pow(d, (double)(TT-1-s));
    for (int s = 0; s < TT; ++s)
        g_coeff[s] = (float)(-0.01 * (1.0 - M) * cs[s]);
    g_dfac = (float)pow(d, (double)TT);
}

// warp dot product over contiguous float4 data
__device__ __forceinline__ float warpdot4(const float4* a, const float4* b, int n4) {
    float s = 0.f;
    for (int i = (threadIdx.x & 31); i < n4; i += 32) {
        float4 x = a[i], y = b[i];
        s += x.x*y.x + x.y*y.y + x.z*y.z + x.w*y.w;
    }
    #pragma unroll
    for (int o = 16; o; o >>= 1) s += __shfl_xor_sync(0xFFFFFFFFu, s, o);
    return s;
}

// ---------------- retrieval path (tiny) ----------------
// q[c] = dot(init_query, Wq[c,:]) + bq[c]
__global__ void k_q(const float* __restrict__ iq, const float* __restrict__ Wq,
                    const float* __restrict__ bq) {
    int w = (blockIdx.x * blockDim.x + threadIdx.x) >> 5;
    if (w >= CC) return;
    float s = warpdot4((const float4*)iq, (const float4*)(Wq + (size_t)w*CC), CC/4);
    if ((threadIdx.x & 31) == 0) g_q[w] = s + bq[w];
}

// h[b,h] = silu( dot(q, sW0[b,h,:]) + sb0[b,h] )
__global__ void k_h(const float* __restrict__ sW0, const float* __restrict__ sb0) {
    int w = (blockIdx.x * blockDim.x + threadIdx.x) >> 5;
    if (w >= BB*HH) return;
    float s = warpdot4((const float4*)g_q, (const float4*)(sW0 + (size_t)w*CC), CC/4) + sb0[w];
    if ((threadIdx.x & 31) == 0) {
        float sig = 1.f / (1.f + expf(-s));
        g_h[w] = s * sig;
    }
}

// pred[b,c] = dot(h[b,:], sW1[b,c,:]) + sb1[b,c]
__global__ void k_pred(const float* __restrict__ sW1, const float* __restrict__ sb1) {
    int w = (blockIdx.x * blockDim.x + threadIdx.x) >> 5;
    if (w >= BB*CC) return;
    int b = w / CC;
    float s = warpdot4((const float4*)(g_h + b*HH), (const float4*)(sW1 + (size_t)w*HH), HH/4)
              + sb1[w];
    if ((threadIdx.x & 31) == 0) g_pred[w] = s;
}

// out[b,c] = dot(pred[b,:], Wo[c,:]) + bo[c]
__global__ void k_out(const float* __restrict__ Wo, const float* __restrict__ bo,
                      float* __restrict__ out) {
    int w = (blockIdx.x * blockDim.x + threadIdx.x) >> 5;
    if (w >= BB*CC) return;
    int b = w / CC, c = w % CC;
    float s = warpdot4((const float4*)(g_pred + b*CC), (const float4*)(Wo + (size_t)c*CC), CC/4)
              + bo[c];
    if ((threadIdx.x & 31) == 0) out[w] = s;
}

// ---------------- memory-update path ----------------
// k/v projections: one warp computes both dots for a (bt, c)
__global__ void k_kv(const float* __restrict__ x,
                     const float* __restrict__ Wk, const float* __restrict__ bk,
                     const float* __restrict__ Wv, const float* __restrict__ bv) {
    int w = (blockIdx.x * blockDim.x + threadIdx.x) >> 5;
    if (w >= BB*TT*CC) return;
    int c = w % CC, bt = w / CC;
    const float4* xr = (const float4*)(x + (size_t)bt*CC);
    const float4* wk = (const float4*)(Wk + (size_t)c*CC);
    const float4* wv = (const float4*)(Wv + (size_t)c*CC);
    float sk = 0.f, sv = 0.f;
    for (int i = (threadIdx.x & 31); i < CC/4; i += 32) {
        float4 xv = xr[i], a = wk[i], bvv = wv[i];
        sk += xv.x*a.x + xv.y*a.y + xv.z*a.z + xv.w*a.w;
        sv += xv.x*bvv.x + xv.y*bvv.y + xv.z*bvv.z + xv.w*bvv.w;
    }
    #pragma unroll
    for (int o = 16; o; o >>= 1) {
        sk += __shfl_xor_sync(0xFFFFFFFFu, sk, o);
        sv += __shfl_xor_sync(0xFFFFFFFFu, sv, o);
    }
    if ((threadIdx.x & 31) == 0) {
        g_k[bt*CC + c] = sk + bk[c];
        g_v[bt*CC + c] = sv + bv[c];
    }
}

// h1[b,t,h] = silu(pre), gfac = silu'(pre); pre = dot(k[b,t,:], sW0[b,h,:]) + sb0
__global__ void k_h1(const float* __restrict__ sW0, const float* __restrict__ sb0) {
    int w = (blockIdx.x * blockDim.x + threadIdx.x) >> 5;
    if (w >= BB*TT*HH) return;
    int h = w % HH, bt = w / HH, b = bt / TT;
    float s = warpdot4((const float4*)(g_k + bt*CC),
                       (const float4*)(sW0 + ((size_t)b*HH + h)*CC), CC/4) + sb0[b*HH + h];
    if ((threadIdx.x & 31) == 0) {
        float sig = 1.f / (1.f + expf(-s));
        g_h1[w]   = s * sig;
        g_gfac[w] = sig * (1.f + s * (1.f - sig));
    }
}

// dp[b,t,c] = dot(h1[b,t,:], sW1[b,c,:]) + sb1[b,c] - v[b,t,c]
__global__ void k_dp(const float* __restrict__ sW1, const float* __restrict__ sb1) {
    int w = (blockIdx.x * blockDim.x + threadIdx.x) >> 5;
    if (w >= BB*TT*CC) return;
    int c = w % CC, bt = w / CC, b = bt / TT;
    float s = warpdot4((const float4*)(g_h1 + bt*HH),
                       (const float4*)(sW1 + ((size_t)b*CC + c)*HH), HH/4) + sb1[b*CC + c];
    if ((threadIdx.x & 31) == 0) g_dp[w] = s - g_v[bt*CC + c];
}

// dh1p[b,t,h] = gfac * sum_c dp[b,t,c] * sW1[b,c,h]   (strided column dot; h coalesced)
__global__ void k_dh1p(const float* __restrict__ sW1) {
    int bt = blockIdx.x / (HH/256);
    int hb = (blockIdx.x % (HH/256)) * 256;
    int b  = bt / TT;
    __shared__ float dps[CC];
    for (int i = threadIdx.x; i < CC; i += 256) dps[i] = g_dp[bt*CC + i];
    __syncthreads();
    int h = hb + threadIdx.x;
    const float* wp = sW1 + (size_t)b*CC*HH + h;
    float acc = 0.f;
    #pragma unroll 8
    for (int c = 0; c < CC; ++c) acc += dps[c] * wp[(size_t)c*HH];
    int idx = bt*HH + h;
    g_dh1p[idx] = acc * g_gfac[idx];
}

// nW0[b,h,c] = dfac*sW0 + sum_t coeff[t]*dh1p[b,t,h]*k[b,t,c]   (block per (b,h))
__global__ void k_nw0(const float* __restrict__ sW0, float* __restrict__ o) {
    int bh = blockIdx.x;
    int b = bh / HH, h = bh % HH;
    __shared__ float sa[TT];
    if (threadIdx.x < TT)
        sa[threadIdx.x] = g_coeff[threadIdx.x] * g_dh1p[(b*TT + threadIdx.x)*HH + h];
    __syncthreads();
    int c = threadIdx.x;           // blockDim.x == CC
    float acc = 0.f;
    #pragma unroll 8
    for (int t = 0; t < TT; ++t) acc += sa[t] * g_k[(b*TT + t)*CC + c];
    size_t idx = ((size_t)b*HH + h)*CC + c;
    o[idx] = g_dfac * sW0[idx] + acc;
}

// nW1[b,c,h] = dfac*sW1 + sum_t coeff[t]*dp[b,t,c]*h1[b,t,h]    (block per (b,c))
__global__ void k_nw1(const float* __restrict__ sW1, float* __restrict__ o) {
    int bc = blockIdx.x;
    int b = bc / CC, c = bc % CC;
    __shared__ float sa[TT];
    if (threadIdx.x < TT)
        sa[threadIdx.x] = g_coeff[threadIdx.x] * g_dp[(b*TT + threadIdx.x)*CC + c];
    __syncthreads();
    int h = threadIdx.x;           // blockDim.x == HH
    float acc = 0.f;
    #pragma unroll 8
    for (int t = 0; t < TT; ++t) acc += sa[t] * g_h1[(b*TT + t)*HH + h];
    size_t idx = ((size_t)b*CC + c)*HH + h;
    o[idx] = g_dfac * sW1[idx] + acc;
}

// biases: nb0[b,h], nb1[b,c]
__global__ void k_nb(const float* __restrict__ sb0, const float* __restrict__ sb1,
                     float* __restrict__ nb0, float* __restrict__ nb1) {
    int i = blockIdx.x * blockDim.x + threadIdx.x;
    if (i < BB*HH) {
        float acc = 0.f;
        #pragma unroll 8
        for (int t = 0; t < TT; ++t) acc += g_coeff[t] * g_dh1p[((i/HH)*TT + t)*HH + (i%HH)];
        nb0[i] = g_dfac * sb0[i] + acc;
    } else if (i < BB*HH + BB*CC) {
        int j = i - BB*HH;
        float acc = 0.f;
        #pragma unroll 8
        for (int t = 0; t < TT; ++t) acc += g_coeff[t] * g_dp[((j/CC)*TT + t)*CC + (j%CC)];
        nb1[j] = g_dfac * sb1[j] + acc;
    }
}

extern "C" void kernel_launch(void* const* d_in, const int* in_sizes, int n_in,
                              void* d_out, int out_size) {
    const float* x   = (const float*)d_in[0];
    const float* Wq  = (const float*)d_in[1];
    const float* bq  = (const float*)d_in[2];
    const float* Wk  = (const float*)d_in[3];
    const float* bk  = (const float*)d_in[4];
    const float* Wv  = (const float*)d_in[5];
    const float* bv  = (const float*)d_in[6];
    const float* Wo  = (const float*)d_in[7];
    const float* bo  = (const float*)d_in[8];
    const float* iq  = (const float*)d_in[9];
    const float* sW0 = (const float*)d_in[10];
    const float* sb0 = (const float*)d_in[11];
    const float* sW1 = (const float*)d_in[12];
    const float* sb1 = (const float*)d_in[13];

    float* out  = (float*)d_out;
    float* o_out = out;                                  // [B,1,C]   768
    float* o_nw0 = o_out + BB*CC;                        // [B,H,C]   589824
    float* o_nb0 = o_nw0 + (size_t)BB*HH*CC;             // [B,H]     1536
    float* o_nw1 = o_nb0 + BB*HH;                        // [B,C,H]   589824
    float* o_nb1 = o_nw1 + (size_t)BB*CC*HH;             // [B,C]     768

    k_coeff<<<1, 32>>>();
    // retrieval path
    k_q   <<<(CC*32 + 255)/256,        256>>>(iq, Wq, bq);
    k_h   <<<(BB*HH*32 + 255)/256,     256>>>(sW0, sb0);
    k_pred<<<(BB*CC*32 + 255)/256,     256>>>(sW1, sb1);
    k_out <<<(BB*CC*32 + 255)/256,     256>>>(Wo, bo, o_out);
    // memory-update path
    k_kv  <<<(BB*TT*CC*32 + 255)/256,  256>>>(x, Wk, bk, Wv, bv);
    k_h1  <<<(BB*TT*HH*32 + 255)/256,  256>>>(sW0, sb0);
    k_dp  <<<(BB*TT*CC*32 + 255)/256,  256>>>(sW1, sb1);
    k_dh1p<<<BB*TT*(HH/256),           256>>>(sW1);
    k_nw0 <<<BB*HH, CC>>>(sW0, o_nw0);
    k_nw1 <<<BB*CC, HH>>>(sW1, o_nw1);
    k_nb  <<<(BB*HH + BB*CC + 255)/256, 256>>>(sb0, sb1, o_nb0, o_nb1);
}

// round 3
// speedup vs baseline: 3.0336x; 3.0336x over previous
#include <cuda_runtime.h>
#include <cuda_bf16.h>
#include <math.h>

#define BB 2
#define TT 64
#define CC 384
#define HH 768
#define BKt 16
#define LDA_S 68   // 64 + 4 pad (keeps float4 alignment, breaks bank conflicts)

// ---------------- scratch (device globals) ----------------
__device__ float g_q[CC];
__device__ float g_h[BB*HH];         // retrieval hidden (post-silu)
__device__ float g_pred[BB*CC];
__device__ float g_k[BB*TT*CC];
__device__ float g_v[BB*TT*CC];
__device__ float g_h1[BB*TT*HH];     // layer-1 PRE-activation (bias included)
__device__ float g_dp[BB*TT*CC];     // p - v (final)
__device__ float g_ds[BB*TT*HH];     // dp @ W1 (pre-gfac)

__device__ __forceinline__ float silu_f(float x) {
    float s = 1.f / (1.f + expf(-x)); return x * s;
}
__device__ __forceinline__ float gfac_f(float x) {
    float s = 1.f / (1.f + expf(-x)); return s * (1.f + x * (1.f - s));
}

__device__ __forceinline__ float warpdot4(const float4* a, const float4* b, int n4) {
    float s = 0.f;
    for (int i = (threadIdx.x & 31); i < n4; i += 32) {
        float4 x = a[i], y = b[i];
        s += x.x*y.x + x.y*y.y + x.z*y.z + x.w*y.w;
    }
    #pragma unroll
    for (int o = 16; o; o >>= 1) s += __shfl_xor_sync(0xFFFFFFFFu, s, o);
    return s;
}

// 64x64 tile * BK=16 slab, 256 threads, 4x4 per thread
__device__ __forceinline__ void core16(const float (*As)[LDA_S], const float (*Bs)[LDA_S],
                                       float (&acc)[4][4], int tm, int tn) {
    #pragma unroll
    for (int kk = 0; kk < BKt; ++kk) {
        float4 a4 = *(const float4*)&As[kk][tm*4];
        float4 b4 = *(const float4*)&Bs[kk][tn*4];
        float av[4] = {a4.x, a4.y, a4.z, a4.w};
        float bv[4] = {b4.x, b4.y, b4.z, b4.w};
        #pragma unroll
        for (int i = 0; i < 4; ++i)
            #pragma unroll
            for (int j = 0; j < 4; ++j)
                acc[i][j] += av[i] * bv[j];
    }
}

// scatter-transpose loader: src row-major [64 rows][K], want S[kk][row]
__device__ __forceinline__ void ldNT(float (*S)[LDA_S], const float* src, int ld,
                                     int kbase, int tid) {
    int r = tid >> 2, ks = (tid & 3) << 2;
    float4 v = *(const float4*)(src + (size_t)r*ld + kbase + ks);
    S[ks+0][r] = v.x; S[ks+1][r] = v.y; S[ks+2][r] = v.z; S[ks+3][r] = v.w;
}

// ============================================================================
// K0: init atomic targets with biases, zero g_ds, compute q
// grid = 192 + 384 + 384 + 48 = 1008
// ============================================================================
__global__ void K0(const float* __restrict__ iq, const float* __restrict__ Wq,
                   const float* __restrict__ bq, const float* __restrict__ bk,
                   const float* __restrict__ bv, const float* __restrict__ sb0) {
    int blk = blockIdx.x, tid = threadIdx.x;
    if (blk < 192) {                               // k,v = bias
        int i = blk*256 + tid;
        int c = i % CC;
        g_k[i] = bk[c];
        g_v[i] = bv[c];
    } else if (blk < 192 + 384) {                  // h1pre = sb0
        int i = (blk - 192)*256 + tid;
        g_h1[i] = sb0[(i/(TT*HH))*HH + (i % HH)];
    } else if (blk < 192 + 768) {                  // ds = 0
        g_ds[(blk - 576)*256 + tid] = 0.f;
    } else {                                       // q = iq @ Wq^T + bq (384 warps)
        int w = (blk - 960)*8 + (tid >> 5);
        float s = warpdot4((const float4*)iq, (const float4*)(Wq + (size_t)w*CC), CC/4);
        if ((tid & 31) == 0) g_q[w] = s + bq[w];
    }
}

// ============================================================================
// K1: kv GEMM (96 blocks, splitK=4)  +  h retrieval (192 blocks)
// ============================================================================
__global__ void K1(const float* __restrict__ x, const float* __restrict__ Wk,
                   const float* __restrict__ Wv, const float* __restrict__ sW0,
                   const float* __restrict__ sb0) {
    __shared__ float As[BKt][LDA_S], Bs[BKt][LDA_S];
    int blk = blockIdx.x, tid = threadIdx.x;
    if (blk < 96) {
        int kc = blk & 3, tile = blk >> 2;
        int tr = tile / 12, tc = tile % 12;
        int m0 = tr*64, n0 = tc*64, k0 = kc*96;
        const float* Wn = (n0 < CC) ? Wk + (size_t)n0*CC : Wv + (size_t)(n0-CC)*CC;
        float acc[4][4] = {};
        for (int kt = 0; kt < 6; ++kt) {
            int kb = k0 + kt*BKt;
            ldNT(As, x + (size_t)m0*CC, CC, kb, tid);
            ldNT(Bs, Wn, CC, kb, tid);
            __syncthreads();
            core16(As, Bs, acc, tid & 15, tid >> 4);
            __syncthreads();
        }
        int tm = tid & 15, tn = tid >> 4;
        float* dst = (n0 < CC) ? g_k : g_v;
        int nb = (n0 < CC) ? n0 : n0 - CC;
        #pragma unroll
        for (int i = 0; i < 4; ++i) {
            int m = m0 + tm*4 + i;
            #pragma unroll
            for (int j = 0; j < 4; ++j)
                atomicAdd(&dst[(size_t)m*CC + nb + tn*4 + j], acc[i][j]);
        }
    } else {  // h[b,h] = silu(q . sW0[b,h,:] + sb0)
        int w = (blk - 96)*8 + (tid >> 5);
        float s = warpdot4((const float4*)g_q, (const float4*)(sW0 + (size_t)w*CC), CC/4)
                  + sb0[w];
        if ((tid & 31) == 0) g_h[w] = silu_f(s);
    }
}

// ============================================================================
// K2: h1pre GEMM (96) + dp init (192) + pred retrieval (96)
// ============================================================================
__global__ void K2(const float* __restrict__ sW0, const float* __restrict__ sW1,
                   const float* __restrict__ sb1) {
    __shared__ float As[BKt][LDA_S], Bs[BKt][LDA_S];
    int blk = blockIdx.x, tid = threadIdx.x;
    if (blk < 96) {
        int kc = blk & 3, tile = blk >> 2;
        int bb = tile / 12, tc = tile % 12;
        int n0 = tc*64, k0 = kc*96;
        float acc[4][4] = {};
        for (int kt = 0; kt < 6; ++kt) {
            int kb = k0 + kt*BKt;
            ldNT(As, g_k + (size_t)bb*TT*CC, CC, kb, tid);
            ldNT(Bs, sW0 + (size_t)(bb*HH + n0)*CC, CC, kb, tid);
            __syncthreads();
            core16(As, Bs, acc, tid & 15, tid >> 4);
            __syncthreads();
        }
        int tm = tid & 15, tn = tid >> 4;
        #pragma unroll
        for (int i = 0; i < 4; ++i) {
            int m = tm*4 + i;
            #pragma unroll
            for (int j = 0; j < 4; ++j)
                atomicAdd(&g_h1[(size_t)(bb*TT + m)*HH + n0 + tn*4 + j], acc[i][j]);
        }
    } else if (blk < 288) {   // dp = sb1 - v
        int i = (blk - 96)*256 + tid;
        int b = i / (TT*CC), c = i % CC;
        g_dp[i] = sb1[b*CC + c] - g_v[i];
    } else {                  // pred[b,c] = h . sW1[b,c,:] + sb1
        int w = (blk - 288)*8 + (tid >> 5);
        int b = w / CC;
        float s = warpdot4((const float4*)(g_h + b*HH),
                           (const float4*)(sW1 + (size_t)w*HH), HH/4) + sb1[w];
        if ((tid & 31) == 0) g_pred[w] = s;
    }
}

// ============================================================================
// K3: dp GEMM (48, A=silu(h1pre), K=768 split 4) + out retrieval (96)
// ============================================================================
__global__ void K3(const float* __restrict__ sW1, const float* __restrict__ Wo,
                   const float* __restrict__ bo, float* __restrict__ o_out) {
    __shared__ float As[BKt][LDA_S], Bs[BKt][LDA_S];
    int blk = blockIdx.x, tid = threadIdx.x;
    if (blk < 48) {
        int kc = blk & 3, tile = blk >> 2;
        int bb = tile / 6, tc = tile % 6;
        int n0 = tc*64, k0 = kc*192;
        float acc[4][4] = {};
        for (int kt = 0; kt < 12; ++kt) {
            int kb = k0 + kt*BKt;
            {   // A with silu applied on load
                int r = tid >> 2, ks = (tid & 3) << 2;
                float4 v = *(const float4*)(g_h1 + (size_t)(bb*TT + r)*HH + kb + ks);
                As[ks+0][r] = silu_f(v.x); As[ks+1][r] = silu_f(v.y);
                As[ks+2][r] = silu_f(v.z); As[ks+3][r] = silu_f(v.w);
            }
            ldNT(Bs, sW1 + (size_t)(bb*CC + n0)*HH, HH, kb, tid);
            __syncthreads();
            core16(As, Bs, acc, tid & 15, tid >> 4);
            __syncthreads();
        }
        int tm = tid & 15, tn = tid >> 4;
        #pragma unroll
        for (int i = 0; i < 4; ++i) {
            int m = tm*4 + i;
            #pragma unroll
            for (int j = 0; j < 4; ++j)
                atomicAdd(&g_dp[(size_t)(bb*TT + m)*CC + n0 + tn*4 + j], acc[i][j]);
        }
    } else {   // out[b,c] = pred . Wo[c,:] + bo
        int w = (blk - 48)*8 + (tid >> 5);
        int b = w / CC, c = w % CC;
        float s = warpdot4((const float4*)(g_pred + b*CC),
                           (const float4*)(Wo + (size_t)c*CC), CC/4) + bo[c];
        if ((tid & 31) == 0) o_out[w] = s;
    }
}

// ============================================================================
// K4: ds GEMM = dp @ sW1 (NN on B), 96 blocks, splitK=4
// ============================================================================
__global__ void K4(const float* __restrict__ sW1) {
    __shared__ float As[BKt][LDA_S], Bs[BKt][LDA_S];
    int blk = blockIdx.x, tid = threadIdx.x;
    int kc = blk & 3, tile = blk >> 2;
    int bb = tile / 12, tc = tile % 12;
    int n0 = tc*64, k0 = kc*96;
    float acc[4][4] = {};
    for (int kt = 0; kt < 6; ++kt) {
        int kb = k0 + kt*BKt;
        ldNT(As, g_dp + (size_t)bb*TT*CC, CC, kb, tid);
        {   // B NN: Bs[kk][n] = sW1[b, kb+kk, n0+n]
            int kk = tid >> 4, cs = (tid & 15) << 2;
            float4 v = *(const float4*)(sW1 + (size_t)(bb*CC + kb + kk)*HH + n0 + cs);
            *(float4*)&Bs[kk][cs] = v;
        }
        __syncthreads();
        core16(As, Bs, acc, tid & 15, tid >> 4);
        __syncthreads();
    }
    int tm = tid & 15, tn = tid >> 4;
    #pragma unroll
    for (int i = 0; i < 4; ++i) {
        int m = tm*4 + i;
        #pragma unroll
        for (int j = 0; j < 4; ++j)
            atomicAdd(&g_ds[(size_t)(bb*TT + m)*HH + n0 + tn*4 + j], acc[i][j]);
    }
}

// ============================================================================
// K5: nw0 (144) + nw1 (144) + biases (9).  coeff/dfac closed-form in smem.
// ============================================================================
__global__ void K5(const float* __restrict__ sW0, const float* __restrict__ sW1,
                   const float* __restrict__ sb0, const float* __restrict__ sb1,
                   float* __restrict__ o_nw0, float* __restrict__ o_nb0,
                   float* __restrict__ o_nw1, float* __restrict__ o_nb1) {
    __shared__ float As[BKt][LDA_S], Bs[BKt][LDA_S];
    __shared__ float coeff_s[TT];
    __shared__ float dfac_s;
    int blk = blockIdx.x, tid = threadIdx.x;
    if (tid < TT) {
        double d = 0.999, r = 0.9 / 0.999;
        double cs = pow(d, (double)(TT-1-tid)) * (pow(r, (double)(TT-tid)) - 1.0) / (r - 1.0);
        coeff_s[tid] = (float)(-0.01 * 0.1 * cs);   // -LR*(1-MOM)*c_t
    }
    if (tid == TT) dfac_s = (float)pow(0.999, (double)TT);
    __syncthreads();

    if (blk < 288) {
        bool is0 = blk < 144;
        int tile = is0 ? blk : blk - 144;
        int bb = tile / 72, rr = tile % 72;
        int tr = is0 ? rr/6 : rr/12;
        int tc = is0 ? rr%6 : rr%12;
        int m0 = tr*64, n0 = tc*64;
        float acc[4][4] = {};
        for (int kt = 0; kt < 4; ++kt) {
            int kk = tid >> 4, ms = (tid & 15) << 2;
            int t = kt*BKt + kk;
            float cf = coeff_s[t];
            if (is0) {  // A[t][h] = coeff*gfac(h1pre)*ds ; B[t][c] = k
                size_t ia = (size_t)(bb*TT + t)*HH + m0 + ms;
                float4 dv = *(const float4*)&g_ds[ia];
                float4 pv = *(const float4*)&g_h1[ia];
                As[kk][ms+0] = cf * dv.x * gfac_f(pv.x);
                As[kk][ms+1] = cf * dv.y * gfac_f(pv.y);
                As[kk][ms+2] = cf * dv.z * gfac_f(pv.z);
                As[kk][ms+3] = cf * dv.w * gfac_f(pv.w);
                float4 bv4 = *(const float4*)&g_k[(size_t)(bb*TT + t)*CC + n0 + ms];
                *(float4*)&Bs[kk][ms] = bv4;
            } else {    // A[t][c] = coeff*dp ; B[t][h] = silu(h1pre)
                float4 dv = *(const float4*)&g_dp[(size_t)(bb*TT + t)*CC + m0 + ms];
                As[kk][ms+0] = cf * dv.x; As[kk][ms+1] = cf * dv.y;
                As[kk][ms+2] = cf * dv.z; As[kk][ms+3] = cf * dv.w;
                float4 pv = *(const float4*)&g_h1[(size_t)(bb*TT + t)*HH + n0 + ms];
                Bs[kk][ms+0] = silu_f(pv.x); Bs[kk][ms+1] = silu_f(pv.y);
                Bs[kk][ms+2] = silu_f(pv.z); Bs[kk][ms+3] = silu_f(pv.w);
            }
            __syncthreads();
            core16(As, Bs, acc, tid & 15, tid >> 4);
            __syncthreads();
        }
        int tm = tid & 15, tn = tid >> 4;
        float df = dfac_s;
        if (is0) {
            #pragma unroll
            for (int i = 0; i < 4; ++i) {
                int h = m0 + tm*4 + i;
                #pragma unroll
                for (int j = 0; j < 4; ++j) {
                    size_t idx = (size_t)(bb*HH + h)*CC + n0 + tn*4 + j;
                    o_nw0[idx] = df * sW0[idx] + acc[i][j];
                }
            }
        } else {
            #pragma unroll
            for (int i = 0; i < 4; ++i) {
                int c = m0 + tm*4 + i;
                #pragma unroll
                for (int j = 0; j < 4; ++j) {
                    size_t idx = (size_t)(bb*CC + c)*HH + n0 + tn*4 + j;
                    o_nw1[idx] = df * sW1[idx] + acc[i][j];
                }
            }
        }
    } else {  // biases
        int i = (blk - 288)*256 + tid;
        float df = dfac_s;
        if (i < BB*HH) {
            int b = i / HH, h = i % HH;
            float acc = 0.f;
            #pragma unroll 8
            for (int t = 0; t < TT; ++t) {
                size_t idx = (size_t)(b*TT + t)*HH + h;
                acc += coeff_s[t] * g_ds[idx] * gfac_f(g_h1[idx]);
            }
            o_nb0[i] = df * sb0[i] + acc;
        } else if (i < BB*HH + BB*CC) {
            int j = i - BB*HH;
            int b = j / CC, c = j % CC;
            float acc = 0.f;
            #pragma unroll 8
            for (int t = 0; t < TT; ++t)
                acc += coeff_s[t] * g_dp[(size_t)(b*TT + t)*CC + c];
            o_nb1[j] = df * sb1[j] + acc;
        }
    }
}

// ============================================================================
extern "C" void kernel_launch(void* const* d_in, const int* in_sizes, int n_in,
                              void* d_out, int out_size) {
    const float* x   = (const float*)d_in[0];
    const float* Wq  = (const float*)d_in[1];
    const float* bq  = (const float*)d_in[2];
    const float* Wk  = (const float*)d_in[3];
    const float* bk  = (const float*)d_in[4];
    const float* Wv  = (const float*)d_in[5];
    const float* bv  = (const float*)d_in[6];
    const float* Wo  = (const float*)d_in[7];
    const float* bo  = (const float*)d_in[8];
    const float* iq  = (const float*)d_in[9];
    const float* sW0 = (const float*)d_in[10];
    const float* sb0 = (const float*)d_in[11];
    const float* sW1 = (const float*)d_in[12];
    const float* sb1 = (const float*)d_in[13];

    float* out   = (float*)d_out;
    float* o_out = out;                          // [B,1,C]
    float* o_nw0 = o_out + BB*CC;                // [B,H,C]
    float* o_nb0 = o_nw0 + (size_t)BB*HH*CC;     // [B,H]
    float* o_nw1 = o_nb0 + BB*HH;                // [B,C,H]
    float* o_nb1 = o_nw1 + (size_t)BB*CC*HH;     // [B,C]

    K0<<<1008, 256>>>(iq, Wq, bq, bk, bv, sb0);
    K1<<<288,  256>>>(x, Wk, Wv, sW0, sb0);
    K2<<<384,  256>>>(sW0, sW1, sb1);
    K3<<<144,  256>>>(sW1, Wo, bo, o_out);
    K4<<<96,   256>>>(sW1);
    K5<<<297,  256>>>(sW0, sW1, sb0, sb1, o_nw0, o_nb0, o_nw1, o_nb1);
}